// round 5
// baseline (speedup 1.0000x reference)
#include <cuda_runtime.h>
#include <cstdint>

#define B 16
#define I 256
#define T 8192
#define NSTEP 8189   // T-3 sampled steps
#define TOUT  8190   // T-2 output length

// Scratch (static __device__ arrays; no allocation anywhere)
__device__ unsigned char g_nsp[B * T];       // [b][t]: bits0-1 = normal sample, bit2 = special sample - 1
__device__ unsigned char g_delta[B * T];     // [b][jo]: gather delta in {0,1,2}

// ---------------- Threefry-2x32 (JAX-exact) ----------------
__device__ __forceinline__ void tf2x32(uint32_t k1, uint32_t k2,
                                       uint32_t c0, uint32_t c1,
                                       uint32_t& o0, uint32_t& o1) {
    uint32_t ks2 = k1 ^ k2 ^ 0x1BD11BDAu;
    uint32_t x0 = c0 + k1;
    uint32_t x1 = c1 + k2;
#define TFR(r) { x0 += x1; x1 = __funnelshift_l(x1, x1, (r)); x1 ^= x0; }
    TFR(13) TFR(15) TFR(26) TFR(6)
    x0 += k2;  x1 += ks2 + 1u;
    TFR(17) TFR(29) TFR(16) TFR(24)
    x0 += ks2; x1 += k1 + 2u;
    TFR(13) TFR(15) TFR(26) TFR(6)
    x0 += k1;  x1 += k2 + 3u;
    TFR(17) TFR(29) TFR(16) TFR(24)
    x0 += k2;  x1 += ks2 + 4u;
    TFR(13) TFR(15) TFR(26) TFR(6)
    x0 += ks2; x1 += k1 + 5u;
#undef TFR
    o0 = x0; o1 = x1;
}

// gumbel from 32 random bits, replicating jax._src.random._uniform + gumbel
__device__ __forceinline__ float gumbel_bits(uint32_t bits) {
    const float TINY = 1.17549435e-38f;   // finfo(float32).tiny
    float f = __uint_as_float((bits >> 9) | 0x3F800000u) - 1.0f;  // [0,1)
    float u = fmaxf(TINY, f + TINY);
    return -logf(-logf(u));
}

// ---------------- Kernel 1: per-(t,b) normal & special samples ----------------
// Block covers 16 t x 16 b; per-step keys deduped through shared memory
// (threefry(seed,(0,t)) computed once per t instead of once per (t,b)).
__global__ __launch_bounds__(256) void kgen(const int* __restrict__ seedp) {
    __shared__ uint2 skey[16];

    int tt = threadIdx.x & 15;          // t within block
    int b  = threadIdx.x >> 4;          // batch
    int t  = blockIdx.x * 16 + tt;

    uint32_t seed_lo = (uint32_t)(*seedp);  // threefry_seed: k1 = seed>>32 = 0

    if (b == 0) {
        uint32_t kx, ky;
        tf2x32(0u, seed_lo, 0u, (uint32_t)t, kx, ky);   // split -> per-step key
        skey[tt] = make_uint2(kx, ky);
    }
    __syncthreads();

    if (t >= NSTEP) return;
    uint2 key = skey[tt];

    float g0, g1, g2;
    {
        uint32_t o0, o1;
        tf2x32(key.x, key.y, 0u, (uint32_t)(b * 3 + 0), o0, o1);
        g0 = gumbel_bits(o0 ^ o1);
        tf2x32(key.x, key.y, 0u, (uint32_t)(b * 3 + 1), o0, o1);
        g1 = gumbel_bits(o0 ^ o1);
        tf2x32(key.x, key.y, 0u, (uint32_t)(b * 3 + 2), o0, o1);
        g2 = gumbel_bits(o0 ^ o1);
    }

    const double pd = 0.1, sd = 1.0 - 2.0 * 0.1;
    float lp  = logf(0.1f);
    float ls  = logf(0.8f);
    float l1s = logf((float)(sd / (pd + sd)));  // special row k=1
    float l2s = logf((float)(pd / (pd + sd)));  // special row k=2  (k=0 is -inf)

    // normal row argmax (first max wins)
    float v0 = g0 + lp, v1 = g1 + ls, v2 = g2 + lp;
    int n = 0; float best = v0;
    if (v1 > best) { best = v1; n = 1; }
    if (v2 > best) { n = 2; }

    // special row argmax over {1,2} (index 0 has -inf logit)
    int sp = (g2 + l2s > g1 + l1s) ? 2 : 1;

    g_nsp[b * T + t] = (unsigned char)(n | ((sp - 1) << 2));
}

// ---------------- Kernel 2: parallel FSM scan per batch ----------------
// state v = 3*p2 + p1 in [0,9); special state is v==5.
// step: choice = (v==5) ? sp : n ; v' = 3*(v%3) + choice.
__global__ __launch_bounds__(512) void kscan() {
    int b = blockIdx.x;
    int j = threadIdx.x;               // 0..511, chunk of 16 steps
    __shared__ uint32_t maps[512];

    uint4 wv = *reinterpret_cast<const uint4*>(g_nsp + b * T + j * 16);
    uint32_t w[4] = {wv.x, wv.y, wv.z, wv.w};

    int nvalid = NSTEP - j * 16;
    if (nvalid > 16) nvalid = 16;      // every thread has >= 1 valid step

    // chunk function: class (0..3) -> resulting state
    uint32_t f0, f1, f2, f3;
    {
        uint32_t byt = w[0] & 0xFFu;
        uint32_t n = byt & 3u, sp = 1u + ((byt >> 2) & 1u);
        f0 = n; f1 = 3u + n; f2 = 6u + n; f3 = 6u + sp;
    }
    for (int s = 1; s < nvalid; s++) {
        uint32_t byt = (w[s >> 2] >> ((s & 3) * 8)) & 0xFFu;
        uint32_t n = byt & 3u, sp = 1u + ((byt >> 2) & 1u);
        f0 = (f0 % 3u) * 3u + ((f0 == 5u) ? sp : n);
        f1 = (f1 % 3u) * 3u + ((f1 == 5u) ? sp : n);
        f2 = (f2 % 3u) * 3u + ((f2 == 5u) ? sp : n);
        f3 = (f3 % 3u) * 3u + ((f3 == 5u) ? sp : n);
    }
    maps[j] = f0 | (f1 << 8) | (f2 << 16) | (f3 << 24);
    __syncthreads();

    // Hillis-Steele inclusive scan of chunk-function composition
    for (int off = 1; off < 512; off <<= 1) {
        uint32_t prev = (j >= off) ? maps[j - off] : 0u;
        __syncthreads();
        if (j >= off) {
            uint32_t cur = maps[j];
            uint32_t nm = 0u;
#pragma unroll
            for (int c = 0; c < 4; c++) {
                uint32_t pv = (prev >> (8 * c)) & 0xFFu;
                uint32_t cl = (pv == 5u) ? 3u : (pv % 3u);
                nm |= (((cur >> (8 * cl)) & 0xFFu) << (8 * c));
            }
            maps[j] = nm;
        }
        __syncthreads();
    }

    // entry state: apply prefix (chunks 0..j-1) to init state 4 (class 1)
    uint32_t v = (j == 0) ? 4u : ((maps[j - 1] >> 8) & 0xFFu);

    unsigned char* dp = g_delta + b * T;
    if (j == 0) dp[0] = 1;             // jo=0 fixed index 1
#pragma unroll
    for (int s = 0; s < 16; s++) {
        int t = j * 16 + s;
        if (t < NSTEP) {
            uint32_t byt = (w[s >> 2] >> ((s & 3) * 8)) & 0xFFu;
            uint32_t n = byt & 3u, sp = 1u + ((byt >> 2) & 1u);
            uint32_t ch = (v == 5u) ? sp : n;
            dp[t + 1] = (unsigned char)ch;
            v = (v % 3u) * 3u + ch;
        }
    }
}

// ---------------- Kernel 3: barrier-free warp-local gather ----------------
// Each warp handles 128 consecutive outputs of one row: 32 aligned LDG.128
// (one float4/lane) + one 8B halo broadcast from lane 0; neighbor elements
// via shfl_down; deltas as one coalesced uchar4/lane; stores STG.128 on
// 16B-aligned rows, 2x STG.64 otherwise. No smem, no barriers.
__global__ __launch_bounds__(256) void kgather(const float* __restrict__ x,
                                               float* __restrict__ y) {
    int g    = blockIdx.x * 8 + (threadIdx.x >> 5);  // global warp id
    int lane = threadIdx.x & 31;
    int row  = g >> 6;                               // b*I + i
    int wseg = g & 63;
    int wb   = wseg << 7;                            // warp base within row
    int b    = row >> 8;
    bool last = (wseg == 63);                        // row tail: 126 valid outputs

    const float* xr = x + (size_t)row * T + wb;
    float4 a = __ldg(reinterpret_cast<const float4*>(xr) + lane);

    // halo: x[wb+128], x[wb+129] (absent for the last warp; unused there)
    float ex0 = 0.f, ex1 = 0.f;
    if (!last && lane == 0) {
        float2 e = __ldg(reinterpret_cast<const float2*>(xr + 128));
        ex0 = e.x; ex1 = e.y;
    }
    ex0 = __shfl_sync(0xFFFFFFFFu, ex0, 0);
    ex1 = __shfl_sync(0xFFFFFFFFu, ex1, 0);

    float nx = __shfl_down_sync(0xFFFFFFFFu, a.x, 1);
    float ny = __shfl_down_sync(0xFFFFFFFFu, a.y, 1);
    if (lane == 31) { nx = ex0; ny = ex1; }

    uchar4 dd = *reinterpret_cast<const uchar4*>(g_delta + (size_t)b * T + wb + lane * 4);

    float o0 = (dd.x == 0) ? a.x : ((dd.x == 1) ? a.y : a.z);
    float o1 = (dd.y == 0) ? a.y : ((dd.y == 1) ? a.z : a.w);
    float o2 = (dd.z == 0) ? a.z : ((dd.z == 1) ? a.w : nx);
    float o3 = (dd.w == 0) ? a.w : ((dd.w == 1) ? nx : ny);

    float* yr = y + (size_t)row * TOUT + wb + lane * 4;
    if (!last) {
        if ((row & 1) == 0) {
            // even rows: y row base is 16B-aligned -> STG.128
            *reinterpret_cast<float4*>(yr) = make_float4(o0, o1, o2, o3);
        } else {
            *reinterpret_cast<float2*>(yr)     = make_float2(o0, o1);
            *reinterpret_cast<float2*>(yr + 2) = make_float2(o2, o3);
        }
    } else {
        // last warp: outputs valid only for jo < 8190 (lane 31 keeps 2 of 4)
        *reinterpret_cast<float2*>(yr) = make_float2(o0, o1);
        if (lane < 31)
            *reinterpret_cast<float2*>(yr + 2) = make_float2(o2, o3);
    }
}

extern "C" void kernel_launch(void* const* d_in, const int* in_sizes, int n_in,
                              void* d_out, int out_size) {
    const float* x   = (const float*)d_in[0];
    const int* seedp = (const int*)d_in[1];
    float* y = (float*)d_out;

    kgen<<<(NSTEP + 15) / 16, 256>>>(seedp);
    kscan<<<B, 512>>>();
    // B*I rows * 64 warps/row, 8 warps per block
    kgather<<<(B * I * 64) / 8, 256>>>(x, y);
}

// round 6
// speedup vs baseline: 1.0419x; 1.0419x over previous
#include <cuda_runtime.h>
#include <cstdint>

#define B 16
#define I 256
#define T 8192
#define NSTEP 8189   // T-3 sampled steps
#define TOUT  8190   // T-2 output length

// Scratch (static __device__ arrays; no allocation anywhere)
__device__ unsigned char g_nsp[B * T];       // [b][t]: bits0-1 = normal sample, bit2 = special sample - 1
__device__ unsigned char g_delta[B * T];     // [b][jo]: gather delta in {0,1,2}

// ---------------- Threefry-2x32 (JAX-exact) ----------------
__device__ __forceinline__ void tf2x32(uint32_t k1, uint32_t k2,
                                       uint32_t c0, uint32_t c1,
                                       uint32_t& o0, uint32_t& o1) {
    uint32_t ks2 = k1 ^ k2 ^ 0x1BD11BDAu;
    uint32_t x0 = c0 + k1;
    uint32_t x1 = c1 + k2;
#define TFR(r) { x0 += x1; x1 = __funnelshift_l(x1, x1, (r)); x1 ^= x0; }
    TFR(13) TFR(15) TFR(26) TFR(6)
    x0 += k2;  x1 += ks2 + 1u;
    TFR(17) TFR(29) TFR(16) TFR(24)
    x0 += ks2; x1 += k1 + 2u;
    TFR(13) TFR(15) TFR(26) TFR(6)
    x0 += k1;  x1 += k2 + 3u;
    TFR(17) TFR(29) TFR(16) TFR(24)
    x0 += k2;  x1 += ks2 + 4u;
    TFR(13) TFR(15) TFR(26) TFR(6)
    x0 += ks2; x1 += k1 + 5u;
#undef TFR
    o0 = x0; o1 = x1;
}

// gumbel from 32 random bits, replicating jax._src.random._uniform + gumbel
__device__ __forceinline__ float gumbel_bits(uint32_t bits) {
    const float TINY = 1.17549435e-38f;   // finfo(float32).tiny
    float f = __uint_as_float((bits >> 9) | 0x3F800000u) - 1.0f;  // [0,1)
    float u = fmaxf(TINY, f + TINY);
    return -logf(-logf(u));
}

// ---------------- Kernel 1: per-(t,b,k) draws, 3-way split ----------------
// 768 threads = 16 t x 16 b x 3 k. Each thread does ONE draw threefry+gumbel
// (short critical path); gumbels combined through smem by the k==0 threads.
__global__ __launch_bounds__(768) void kgen(const int* __restrict__ seedp) {
    __shared__ uint2 skey[16];
    __shared__ float sg[3 * 256];

    int tid = threadIdx.x;
    int k   = tid >> 8;                 // 0..2
    int idx = tid & 255;                // (tt, b)
    int tt  = idx & 15;
    int b   = idx >> 4;
    int t   = blockIdx.x * 16 + tt;

    uint32_t seed_lo = (uint32_t)(*seedp);  // threefry_seed: k1 = seed>>32 = 0

    if (tid < 16) {
        uint32_t kx, ky;
        tf2x32(0u, seed_lo, 0u, (uint32_t)(blockIdx.x * 16 + tid), kx, ky);
        skey[tid] = make_uint2(kx, ky);
    }
    __syncthreads();

    uint2 key = skey[tt];
    uint32_t o0, o1;
    tf2x32(key.x, key.y, 0u, (uint32_t)(b * 3 + k), o0, o1);
    sg[k * 256 + idx] = gumbel_bits(o0 ^ o1);
    __syncthreads();

    if (k == 0 && t < NSTEP) {
        float g0 = sg[idx];
        float g1 = sg[256 + idx];
        float g2 = sg[512 + idx];

        const double pd = 0.1, sd = 1.0 - 2.0 * 0.1;
        float lp  = logf(0.1f);
        float ls  = logf(0.8f);
        float l1s = logf((float)(sd / (pd + sd)));  // special row k=1
        float l2s = logf((float)(pd / (pd + sd)));  // special row k=2  (k=0 is -inf)

        // normal row argmax (first max wins)
        float v0 = g0 + lp, v1 = g1 + ls, v2 = g2 + lp;
        int n = 0; float best = v0;
        if (v1 > best) { best = v1; n = 1; }
        if (v2 > best) { n = 2; }

        // special row argmax over {1,2} (index 0 has -inf logit)
        int sp = (g2 + l2s > g1 + l1s) ? 2 : 1;

        g_nsp[b * T + t] = (unsigned char)(n | ((sp - 1) << 2));
    }
}

// ---------------- Kernel 2: parallel FSM scan per batch ----------------
// state v = 3*p2 + p1 in [0,9); special state is v==5.
// step: choice = (v==5) ? sp : n ; v' = 3*(v%3) + choice.
__global__ __launch_bounds__(512) void kscan() {
    int b = blockIdx.x;
    int j = threadIdx.x;               // 0..511, chunk of 16 steps
    __shared__ uint32_t maps[512];

    uint4 wv = *reinterpret_cast<const uint4*>(g_nsp + b * T + j * 16);
    uint32_t w[4] = {wv.x, wv.y, wv.z, wv.w};

    int nvalid = NSTEP - j * 16;
    if (nvalid > 16) nvalid = 16;      // every thread has >= 1 valid step

    // chunk function: class (0..3) -> resulting state
    uint32_t f0, f1, f2, f3;
    {
        uint32_t byt = w[0] & 0xFFu;
        uint32_t n = byt & 3u, sp = 1u + ((byt >> 2) & 1u);
        f0 = n; f1 = 3u + n; f2 = 6u + n; f3 = 6u + sp;
    }
    for (int s = 1; s < nvalid; s++) {
        uint32_t byt = (w[s >> 2] >> ((s & 3) * 8)) & 0xFFu;
        uint32_t n = byt & 3u, sp = 1u + ((byt >> 2) & 1u);
        f0 = (f0 % 3u) * 3u + ((f0 == 5u) ? sp : n);
        f1 = (f1 % 3u) * 3u + ((f1 == 5u) ? sp : n);
        f2 = (f2 % 3u) * 3u + ((f2 == 5u) ? sp : n);
        f3 = (f3 % 3u) * 3u + ((f3 == 5u) ? sp : n);
    }
    maps[j] = f0 | (f1 << 8) | (f2 << 16) | (f3 << 24);
    __syncthreads();

    // Hillis-Steele inclusive scan of chunk-function composition
    for (int off = 1; off < 512; off <<= 1) {
        uint32_t prev = (j >= off) ? maps[j - off] : 0u;
        __syncthreads();
        if (j >= off) {
            uint32_t cur = maps[j];
            uint32_t nm = 0u;
#pragma unroll
            for (int c = 0; c < 4; c++) {
                uint32_t pv = (prev >> (8 * c)) & 0xFFu;
                uint32_t cl = (pv == 5u) ? 3u : (pv % 3u);
                nm |= (((cur >> (8 * cl)) & 0xFFu) << (8 * c));
            }
            maps[j] = nm;
        }
        __syncthreads();
    }

    // entry state: apply prefix (chunks 0..j-1) to init state 4 (class 1)
    uint32_t v = (j == 0) ? 4u : ((maps[j - 1] >> 8) & 0xFFu);

    unsigned char* dp = g_delta + b * T;
    if (j == 0) dp[0] = 1;             // jo=0 fixed index 1
#pragma unroll
    for (int s = 0; s < 16; s++) {
        int t = j * 16 + s;
        if (t < NSTEP) {
            uint32_t byt = (w[s >> 2] >> ((s & 3) * 8)) & 0xFFu;
            uint32_t n = byt & 3u, sp = 1u + ((byt >> 2) & 1u);
            uint32_t ch = (v == 5u) ? sp : n;
            dp[t + 1] = (unsigned char)ch;
            v = (v % 3u) * 3u + ch;
        }
    }
}

// ---------------- Kernel 3: barrier-free warp gather, 8 outputs/thread ----
// Warp covers 256 consecutive outputs of one row. Per lane: 2 front-batched
// LDG.128 (streaming .cs), halo via shfl, deltas as one uint2, stores .cs.
__global__ __launch_bounds__(256) void kgather(const float* __restrict__ x,
                                               float* __restrict__ y) {
    int g    = blockIdx.x * 8 + (threadIdx.x >> 5);  // global warp id
    int lane = threadIdx.x & 31;
    int row  = g >> 5;                               // b*I + i  (32 warps/row)
    int wseg = g & 31;
    int wb   = wseg << 8;                            // warp base within row
    int b    = row >> 8;
    bool last = (wseg == 31);                        // row tail warp

    const float* xr = x + (size_t)row * T + wb;
    float4 a = __ldcs(reinterpret_cast<const float4*>(xr) + lane * 2);
    float4 c = __ldcs(reinterpret_cast<const float4*>(xr) + lane * 2 + 1);
    uint2 dd = *reinterpret_cast<const uint2*>(g_delta + (size_t)b * T + wb + lane * 8);

    // halo: x[wb+256], x[wb+257] (not needed for last warp)
    float ex0 = 0.f, ex1 = 0.f;
    if (!last && lane == 0) {
        float2 e = __ldg(reinterpret_cast<const float2*>(xr + 256));
        ex0 = e.x; ex1 = e.y;
    }
    ex0 = __shfl_sync(0xFFFFFFFFu, ex0, 0);
    ex1 = __shfl_sync(0xFFFFFFFFu, ex1, 0);

    float nx = __shfl_down_sync(0xFFFFFFFFu, a.x, 1);
    float ny = __shfl_down_sync(0xFFFFFFFFu, a.y, 1);
    if (lane == 31) { nx = ex0; ny = ex1; }

    float rr[10] = {a.x, a.y, a.z, a.w, c.x, c.y, c.z, c.w, nx, ny};
    float o[8];
#pragma unroll
    for (int q = 0; q < 8; q++) {
        uint32_t d = ((q < 4 ? dd.x >> (8 * q) : dd.y >> (8 * (q - 4))) & 3u);
        o[q] = (d == 0) ? rr[q] : ((d == 1) ? rr[q + 1] : rr[q + 2]);
    }

    float* yr = y + (size_t)row * TOUT + wb + lane * 8;
    bool tail = last && (lane == 31);                // outputs 8184..8191; valid < 8190
    if (!tail) {
        if ((row & 1) == 0) {
            __stcs(reinterpret_cast<float4*>(yr),     make_float4(o[0], o[1], o[2], o[3]));
            __stcs(reinterpret_cast<float4*>(yr) + 1, make_float4(o[4], o[5], o[6], o[7]));
        } else {
            __stcs(reinterpret_cast<float2*>(yr),     make_float2(o[0], o[1]));
            __stcs(reinterpret_cast<float2*>(yr) + 1, make_float2(o[2], o[3]));
            __stcs(reinterpret_cast<float2*>(yr) + 2, make_float2(o[4], o[5]));
            __stcs(reinterpret_cast<float2*>(yr) + 3, make_float2(o[6], o[7]));
        }
    } else {
        __stcs(reinterpret_cast<float2*>(yr),     make_float2(o[0], o[1]));
        __stcs(reinterpret_cast<float2*>(yr) + 1, make_float2(o[2], o[3]));
        __stcs(reinterpret_cast<float2*>(yr) + 2, make_float2(o[4], o[5]));
    }
}

extern "C" void kernel_launch(void* const* d_in, const int* in_sizes, int n_in,
                              void* d_out, int out_size) {
    const float* x   = (const float*)d_in[0];
    const int* seedp = (const int*)d_in[1];
    float* y = (float*)d_out;

    kgen<<<(NSTEP + 15) / 16, 768>>>(seedp);
    kscan<<<B, 512>>>();
    // B*I rows * 32 warps/row, 8 warps per block
    kgather<<<(B * I * 32) / 8, 256>>>(x, y);
}